// round 9
// baseline (speedup 1.0000x reference)
#include <cuda_runtime.h>
#include <cuda_bf16.h>
#include <cstdint>

#define Hh   128
#define Ww   128
#define HW   16384
#define Cc   128
#define NP   9
#define OUTC 256
#define Bb   4
#define BK   64
#define NT   18          // K tiles (K = 1152)
#define NPX  128         // pixels per CTA (one image row)
#define NTHR 512
#define NJOB (Bb * Hh)   // 512 row-jobs

typedef unsigned long long ull;
typedef unsigned int u32;

// -------- device scratch --------
__device__ float g_offset[Bb * 2 * NP * HW];          // (b, 18, H, W)
__device__ unsigned g_wmax;                            // absmax(w_conv) bits (zero-init)
// quantized weights: [tile][o][0:64]=hi digits, [64:128]=lo digits (radix-256)
__device__ signed char g_wq[NT * OUTC * 128];
// quantized, swizzled B images per job/tile (written by pass1, read by pass2)
__device__ signed char g_bq[(size_t)NJOB * NT * 16384];

// ---------------- helpers ----------------
__device__ __forceinline__ u32 smem_u32(const void* p) {
    u32 a;
    asm("{ .reg .u64 t; cvta.to.shared.u64 t, %1; cvt.u32.u64 %0, t; }" : "=r"(a) : "l"(p));
    return a;
}
__device__ __forceinline__ void ldsm_x4(u32& r0, u32& r1, u32& r2, u32& r3, u32 addr) {
    asm volatile("ldmatrix.sync.aligned.m8n8.x4.shared.b16 {%0,%1,%2,%3}, [%4];"
                 : "=r"(r0), "=r"(r1), "=r"(r2), "=r"(r3) : "r"(addr));
}
__device__ __forceinline__ void mma_s8(int* d, const u32* a, const u32* b) {
    asm("mma.sync.aligned.m16n8k32.row.col.s32.s8.s8.s32 "
        "{%0,%1,%2,%3},{%4,%5,%6,%7},{%8,%9},{%0,%1,%2,%3};"
        : "+r"(d[0]), "+r"(d[1]), "+r"(d[2]), "+r"(d[3])
        : "r"(a[0]), "r"(a[1]), "r"(a[2]), "r"(a[3]), "r"(b[0]), "r"(b[1]));
}
__device__ __forceinline__ u32 swz(u32 off) { return off ^ ((off >> 3) & 0x70); }

__device__ __forceinline__ void cp_async16(u32 dst, const void* src) {
    asm volatile("cp.async.cg.shared.global [%0], [%1], 16;" :: "r"(dst), "l"(src));
}
#define CP_COMMIT() asm volatile("cp.async.commit_group;" ::: "memory")
#define CP_WAIT0()  asm volatile("cp.async.wait_group 0;" ::: "memory")

// packed f32x2 helpers (offset conv)
__device__ __forceinline__ void ffma2(ull& d, ull a, ull b) {
    asm("fma.rn.f32x2 %0, %1, %2, %0;" : "+l"(d) : "l"(a), "l"(b));
}
__device__ __forceinline__ ull pack2(float lo, float hi) {
    ull r; asm("mov.b64 %0, {%1, %2};" : "=l"(r) : "f"(lo), "f"(hi)); return r;
}
__device__ __forceinline__ float2 unpack2(ull v) {
    float2 f; asm("mov.b64 {%0, %1}, %2;" : "=f"(f.x), "=f"(f.y) : "l"(v)); return f;
}

// ======================================================================
// Kernel 0: absmax(w_conv)
// ======================================================================
__global__ void wmax_k(const float* __restrict__ wc) {
    float m = 0.f;
    for (int i = blockIdx.x * 256 + threadIdx.x; i < OUTC * Cc * NP; i += gridDim.x * 256)
        m = fmaxf(m, fabsf(wc[i]));
#pragma unroll
    for (int s = 16; s > 0; s >>= 1)
        m = fmaxf(m, __shfl_xor_sync(0xFFFFFFFFu, m, s));
    if ((threadIdx.x & 31) == 0)
        atomicMax(&g_wmax, __float_as_uint(m));
}

// ======================================================================
// Kernel 1: quantize + transpose w_conv -> g_wq [tile][o][hi|lo]
// ======================================================================
__global__ void wtrans_k(const float* __restrict__ wc) {
    int i = blockIdx.x * 256 + threadIdx.x;            // 0 .. NT*256*16-1
    if (i >= NT * OUTC * 16) return;
    int jq = i & 15;
    int o  = (i >> 4) & 255;
    int tt = i >> 12;
    float invq = 16383.0f / __uint_as_float(g_wmax);
    u32 hi4 = 0, lo4 = 0;
#pragma unroll
    for (int jj = 0; jj < 4; jj++) {
        int j = jq * 4 + jj;
        int k = tt * 64 + j;
        int n = k >> 7;
        int c = k & 127;
        float w = wc[(o * Cc + c) * NP + n];
        int W = __float2int_rn(w * invq);
        int hi = (W + 128) >> 8;
        int lo = W - (hi << 8);
        hi4 |= (u32)(hi & 255) << (8 * jj);
        lo4 |= (u32)(lo & 255) << (8 * jj);
    }
    *(u32*)(g_wq + tt * 32768 + o * 128 + jq * 4)      = hi4;
    *(u32*)(g_wq + tt * 32768 + o * 128 + 64 + jq * 4) = lo4;
}

// ======================================================================
// Kernel 2: offset conv (proven, unchanged)
// ======================================================================
__global__ void __launch_bounds__(128) offset_conv_k(
    const float* __restrict__ x,
    const float* __restrict__ wp,
    const float* __restrict__ bp)
{
    const int y0 = blockIdx.x * 2;
    const int b  = blockIdx.y;
    const int tx = threadIdx.x;

    __shared__ float xr[4][132];
    __shared__ float ws2[9][18];

    ull acc0[9], acc1[9];
#pragma unroll
    for (int p = 0; p < 9; p++) { acc0[p] = 0ULL; acc1[p] = 0ULL; }

    const float* xb = x + (size_t)b * Cc * HW;

    for (int c = 0; c < Cc; c++) {
        __syncthreads();
        for (int i = tx; i < 162; i += 128) {
            int k  = i / 18;
            int ch = i % 18;
            ws2[k][ch] = wp[ch * (Cc * 9) + c * 9 + k];
        }
        for (int i = tx; i < 4 * 132; i += 128) {
            int r  = i / 132;
            int cc = i % 132;
            int yy = y0 + r - 1;
            int xx = cc - 1;
            float v = 0.f;
            if (yy >= 0 && yy < Hh && xx >= 0 && xx < Ww)
                v = xb[c * HW + yy * Ww + xx];
            xr[r][cc] = v;
        }
        __syncthreads();

#pragma unroll
        for (int k = 0; k < 9; k++) {
            const int ky = k / 3, kx = k % 3;
            float xv0 = xr[ky][tx + kx];
            float xv1 = xr[ky + 1][tx + kx];
            ull x0d = pack2(xv0, xv0);
            ull x1d = pack2(xv1, xv1);
            const ull* wrow = (const ull*)&ws2[k][0];
#pragma unroll
            for (int p = 0; p < 9; p++) {
                ull wpair = wrow[p];
                ffma2(acc0[p], wpair, x0d);
                ffma2(acc1[p], wpair, x1d);
            }
        }
    }

#pragma unroll
    for (int p = 0; p < 9; p++) {
        float2 a0 = unpack2(acc0[p]);
        float2 a1 = unpack2(acc1[p]);
        int ch0 = 2 * p, ch1 = 2 * p + 1;
        float b0 = bp[ch0], b1 = bp[ch1];
        g_offset[((b * 18 + ch0) * Hh + y0) * Ww + tx]     = a0.x + b0;
        g_offset[((b * 18 + ch1) * Hh + y0) * Ww + tx]     = a0.y + b1;
        g_offset[((b * 18 + ch0) * Hh + y0 + 1) * Ww + tx] = a1.x + b0;
        g_offset[((b * 18 + ch1) * Hh + y0 + 1) * Ww + tx] = a1.y + b1;
    }
}

// ======================================================================
// Pass 1: gather + quantize + (hi_w x hi_x) GEMM; stash B image to gmem.
//   out = 64*q_w * A1  (q_x = 1/1024, radix 256: 65536/1024 = 64)
// ======================================================================
#define S_METAW 0                          // float4[1152]  -> 18432
#define S_METAI 18432                      // ushort4[1152] ->  9216
#define P1_BUF0 27648
#define P1_BUFSZ 49152                     // A 32768 | B 16384
#define P1_TOTAL (P1_BUF0 + 2 * P1_BUFSZ)  // 125952
#define P2_BUFSZ 49152
#define P2_TOTAL (2 * P2_BUFSZ)            // 98304

__global__ void __launch_bounds__(NTHR, 1)
ldconv_pass1_k(const float* __restrict__ x, float* __restrict__ out)
{
    extern __shared__ char smem[];
    const u32 sb = smem_u32(smem);
    const int t = threadIdx.x;
    const int wid = t >> 5;
    const int lane = t & 31;
    const int b = blockIdx.y;
    const int y = blockIdx.x;
    const int job = b * Hh + y;

    // ---- bilinear metadata ----
    float4*  metaw = (float4*)(smem + S_METAW);
    ushort4* metai = (ushort4*)(smem + S_METAI);
    for (int task = t; task < NP * NPX; task += NTHR) {
        int n  = task >> 7;
        int px = task & 127;
        float offr = g_offset[((b * 18 + n) * Hh + y) * Ww + px];
        float offc = g_offset[((b * 18 + NP + n) * Hh + y) * Ww + px];
        float pr = (float)y  + (float)(n / 3) + offr;
        float pc = (float)px + (float)(n % 3) + offc;

        float ltr = floorf(pr), ltc = floorf(pc);
        float rbr = ltr + 1.f,  rbc = ltc + 1.f;
        ltr = fminf(fmaxf(ltr, 0.f), 127.f);
        rbr = fminf(fmaxf(rbr, 0.f), 127.f);
        ltc = fminf(fmaxf(ltc, 0.f), 127.f);
        rbc = fminf(fmaxf(rbc, 0.f), 127.f);
        pr  = fminf(fmaxf(pr, 0.f), 127.f);
        pc  = fminf(fmaxf(pc, 0.f), 127.f);

        float dr_lt = 1.f + (ltr - pr);
        float dr_rb = 1.f - (rbr - pr);
        float dc_lt = 1.f + (ltc - pc);
        float dc_rb = 1.f - (rbc - pc);

        float4 g;
        g.x = dr_lt * dc_lt;
        g.y = dr_rb * dc_rb;
        g.z = dr_lt * dc_rb;
        g.w = dr_rb * dc_lt;
        metaw[task] = g;

        int iltr = (int)ltr, iltc = (int)ltc;
        int irbr = (int)rbr, irbc = (int)rbc;
        ushort4 iv;
        iv.x = (unsigned short)(iltr * Ww + iltc);
        iv.y = (unsigned short)(irbr * Ww + irbc);
        iv.z = (unsigned short)(iltr * Ww + irbc);
        iv.w = (unsigned short)(irbr * Ww + iltc);
        metai[task] = iv;
    }
    __syncthreads();

    const float* xb = x + (size_t)b * Cc * HW;
    const int px = t & 127;
    const int kq = t >> 7;        // 16 k per thread

    int acc[4][4][4];
#pragma unroll
    for (int i = 0; i < 4; i++)
#pragma unroll
        for (int j = 0; j < 4; j++)
#pragma unroll
            for (int q = 0; q < 4; q++) acc[i][j][q] = 0;

    const int bo = (wid & 3) * 64;    // warp o-base
    const int bn = (wid >> 2) * 32;   // warp px-base

    auto fillA_async = [&](int tile) {
        const u32 dst = sb + P1_BUF0 + (u32)(tile & 1) * P1_BUFSZ;
        const signed char* src = g_wq + (size_t)tile * 32768;
#pragma unroll
        for (int i = 0; i < 4; i++) {
            int e = t + i * NTHR;     // 16B unit, 0..2047
            u32 sw = swz((u32)(e * 16));
            cp_async16(dst + sw, src + e * 16);
        }
        CP_COMMIT();
    };

    // gather unit: 4 channels x 4 corners -> 16 floats
    float4 gw; ushort4 gi; const float* xc = xb;
    auto setmeta = [&](int tile) {
        const int kg0 = tile * BK + kq * 16;
        const int n   = kg0 >> 7;
        const int c0  = kg0 & 127;
        gw = metaw[n * 128 + px];
        gi = metai[n * 128 + px];
        xc = xb + (size_t)c0 * HW;
    };
    auto ldgu = [&](int u, float* f) {
#pragma unroll
        for (int jj = 0; jj < 4; jj++) {
            const float* p = xc + (size_t)(u * 4 + jj) * HW;
            f[jj * 4 + 0] = __ldg(p + gi.x);
            f[jj * 4 + 1] = __ldg(p + gi.y);
            f[jj * 4 + 2] = __ldg(p + gi.z);
            f[jj * 4 + 3] = __ldg(p + gi.w);
        }
    };
    u32 hib[4], lob[4];
    auto cmbu = [&](int u, const float* f) {
        u32 h4 = 0, l4 = 0;
#pragma unroll
        for (int jj = 0; jj < 4; jj++) {
            float v = gw.x * f[jj*4+0] + gw.y * f[jj*4+1]
                    + gw.z * f[jj*4+2] + gw.w * f[jj*4+3];
            int X  = __float2int_rn(v * 1024.0f);
            int hi = (X + 128) >> 8;
            int lo = X - (hi << 8);
            h4 |= (u32)(hi & 255) << (8 * jj);
            l4 |= (u32)(lo & 255) << (8 * jj);
        }
        hib[u] = h4; lob[u] = l4;
    };
    auto stsB2 = [&](int tile) {
        char* base = smem + P1_BUF0 + (size_t)(tile & 1) * P1_BUFSZ + 32768;
        u32 swh = swz((u32)(px * 128 + kq * 16));
        u32 swl = swz((u32)(px * 128 + 64 + kq * 16));
        *(uint4*)(base + swh) = make_uint4(hib[0], hib[1], hib[2], hib[3]);
        *(uint4*)(base + swl) = make_uint4(lob[0], lob[1], lob[2], lob[3]);
    };

    auto mma_tile = [&](int tile) {
        const u32 buf  = sb + P1_BUF0 + (u32)(tile & 1) * P1_BUFSZ;
        const u32 bufB = buf + 32768;
        u32 a[4][4], bf[4][2];
#pragma unroll
        for (int ks = 0; ks < 2; ks++) {
#pragma unroll
            for (int j = 0; j < 2; j++) {
                int nrow = bn + j * 16 + (lane & 7) + ((lane >> 4) << 3);
                int kb   = ks * 32 + ((lane >> 3) & 1) * 16;
                u32 sw = swz((u32)(nrow * 128 + kb));
                ldsm_x4(bf[2*j][0], bf[2*j][1], bf[2*j+1][0], bf[2*j+1][1], bufB + sw);
            }
#pragma unroll
            for (int mi = 0; mi < 4; mi++) {
                int ar = bo + mi * 16 + (lane & 15);
                int kb = ks * 32 + (lane >> 4) * 16;
                u32 sw = swz((u32)(ar * 128 + kb));
                ldsm_x4(a[mi][0], a[mi][1], a[mi][2], a[mi][3], buf + sw);
            }
#pragma unroll
            for (int mi = 0; mi < 4; mi++)
#pragma unroll
                for (int ng = 0; ng < 4; ng++)
                    mma_s8(acc[mi][ng], a[mi], bf[ng]);
        }
    };

    auto scratch_copy = [&](int tile) {
        const char* src = smem + P1_BUF0 + (size_t)(tile & 1) * P1_BUFSZ + 32768;
        signed char* dst = g_bq + ((size_t)job * NT + tile) * 16384;
#pragma unroll
        for (int i = 0; i < 2; i++) {
            int e = t + i * NTHR;
            *(uint4*)(dst + e * 16) = *(const uint4*)(src + e * 16);
        }
    };

    // ---- prologue ----
    fillA_async(0);
    setmeta(0);
    {
        float f[16];
#pragma unroll
        for (int u = 0; u < 4; u++) { ldgu(u, f); cmbu(u, f); }
        stsB2(0);
    }
    CP_WAIT0();
    __syncthreads();

    // ---- main loop ----
    for (int tile = 0; tile < NT; tile++) {
        const bool nx = (tile + 1 < NT);
        float f0[16], f1[16];
        if (nx) { fillA_async(tile + 1); setmeta(tile + 1); ldgu(0, f0); }
        mma_tile(tile);
        scratch_copy(tile);
        if (nx) {
            ldgu(1, f1); cmbu(0, f0);
            ldgu(2, f0); cmbu(1, f1);
            ldgu(3, f1); cmbu(2, f0);
            cmbu(3, f1);
            stsB2(tile + 1);
        }
        CP_WAIT0();
        __syncthreads();
    }

    // ---- epilogue: out = scale1 * A1 ----
    const float qw = __uint_as_float(g_wmax) * (1.0f / 16383.0f);
    const float s1 = 64.0f * qw;
    const int g  = lane >> 2;
    const int tg = lane & 3;
#pragma unroll
    for (int mi = 0; mi < 4; mi++) {
#pragma unroll
        for (int ng = 0; ng < 4; ng++) {
            int pxo = bn + ng * 8 + 2 * tg;
            int o0  = bo + mi * 16 + g;
            int o1  = o0 + 8;
            float* base = out + (size_t)b * OUTC * HW + y * Ww + pxo;
            *(float2*)(base + (size_t)o0 * HW) =
                make_float2(s1 * (float)acc[mi][ng][0], s1 * (float)acc[mi][ng][1]);
            *(float2*)(base + (size_t)o1 * HW) =
                make_float2(s1 * (float)acc[mi][ng][2], s1 * (float)acc[mi][ng][3]);
        }
    }
}

// ======================================================================
// Pass 2: hi_w x lo_x + lo_w x hi_x + (lo_w x lo_x)/256 from scratch; RMW.
//   out += 0.25*q_w * A2
// ======================================================================
__global__ void __launch_bounds__(NTHR, 1)
ldconv_pass2_k(float* __restrict__ out)
{
    extern __shared__ char smem[];
    const u32 sb = smem_u32(smem);
    const int t = threadIdx.x;
    const int wid = t >> 5;
    const int lane = t & 31;
    const int b = blockIdx.y;
    const int y = blockIdx.x;
    const int job = b * Hh + y;

    int acc[4][4][4];
#pragma unroll
    for (int i = 0; i < 4; i++)
#pragma unroll
        for (int j = 0; j < 4; j++)
#pragma unroll
            for (int q = 0; q < 4; q++) acc[i][j][q] = 0;

    const int bo = (wid & 3) * 64;
    const int bn = (wid >> 2) * 32;

    auto fillAB_async = [&](int tile) {
        const u32 dst = sb + (u32)(tile & 1) * P2_BUFSZ;
        const signed char* srcA = g_wq + (size_t)tile * 32768;
        const signed char* srcB = g_bq + ((size_t)job * NT + tile) * 16384;
#pragma unroll
        for (int i = 0; i < 4; i++) {
            int e = t + i * NTHR;
            cp_async16(dst + swz((u32)(e * 16)), srcA + e * 16);
        }
#pragma unroll
        for (int i = 0; i < 2; i++) {
            int e = t + i * NTHR;
            cp_async16(dst + 32768 + (u32)(e * 16), srcB + e * 16);
        }
        CP_COMMIT();
    };

    auto mma_tile = [&](int tile) {
        const u32 buf  = sb + (u32)(tile & 1) * P2_BUFSZ;
        const u32 bufB = buf + 32768;
        u32 a[4][4], bh[4][2], bl[4][2];
#pragma unroll
        for (int ks = 0; ks < 2; ks++) {
#pragma unroll
            for (int j = 0; j < 2; j++) {
                int nrow = bn + j * 16 + (lane & 7) + ((lane >> 4) << 3);
                int kb   = ks * 32 + ((lane >> 3) & 1) * 16;
                u32 swh = swz((u32)(nrow * 128 + kb));
                u32 swl = swz((u32)(nrow * 128 + 64 + kb));
                ldsm_x4(bh[2*j][0], bh[2*j][1], bh[2*j+1][0], bh[2*j+1][1], bufB + swh);
                ldsm_x4(bl[2*j][0], bl[2*j][1], bl[2*j+1][0], bl[2*j+1][1], bufB + swl);
            }
            // A-hi x B-lo
#pragma unroll
            for (int mi = 0; mi < 4; mi++) {
                int ar = bo + mi * 16 + (lane & 15);
                int kb = ks * 32 + (lane >> 4) * 16;
                u32 sw = swz((u32)(ar * 128 + kb));
                ldsm_x4(a[mi][0], a[mi][1], a[mi][2], a[mi][3], buf + sw);
            }
#pragma unroll
            for (int mi = 0; mi < 4; mi++)
#pragma unroll
                for (int ng = 0; ng < 4; ng++)
                    mma_s8(acc[mi][ng], a[mi], bl[ng]);
            // A-lo x B-hi, then A-lo x B-lo folded at 1/256
#pragma unroll
            for (int mi = 0; mi < 4; mi++) {
                int ar = bo + mi * 16 + (lane & 15);
                int kb = ks * 32 + 64 + (lane >> 4) * 16;
                u32 sw = swz((u32)(ar * 128 + kb));
                ldsm_x4(a[mi][0], a[mi][1], a[mi][2], a[mi][3], buf + sw);
            }
#pragma unroll
            for (int mi = 0; mi < 4; mi++)
#pragma unroll
                for (int ng = 0; ng < 4; ng++) {
                    mma_s8(acc[mi][ng], a[mi], bh[ng]);
                    int tmp[4] = {0, 0, 0, 0};
                    mma_s8(tmp, a[mi], bl[ng]);
#pragma unroll
                    for (int q = 0; q < 4; q++)
                        acc[mi][ng][q] += (tmp[q] + 128) >> 8;
                }
        }
    };

    fillAB_async(0);
    CP_WAIT0();
    __syncthreads();
    for (int tile = 0; tile < NT; tile++) {
        if (tile + 1 < NT) fillAB_async(tile + 1);
        mma_tile(tile);
        CP_WAIT0();
        __syncthreads();
    }

    // ---- epilogue: out += scale2 * A2 ----
    const float qw = __uint_as_float(g_wmax) * (1.0f / 16383.0f);
    const float s2 = 0.25f * qw;
    const int g  = lane >> 2;
    const int tg = lane & 3;
#pragma unroll
    for (int mi = 0; mi < 4; mi++) {
#pragma unroll
        for (int ng = 0; ng < 4; ng++) {
            int pxo = bn + ng * 8 + 2 * tg;
            int o0  = bo + mi * 16 + g;
            int o1  = o0 + 8;
            float* base = out + (size_t)b * OUTC * HW + y * Ww + pxo;
            float2 v0 = *(float2*)(base + (size_t)o0 * HW);
            float2 v1 = *(float2*)(base + (size_t)o1 * HW);
            v0.x += s2 * (float)acc[mi][ng][0];
            v0.y += s2 * (float)acc[mi][ng][1];
            v1.x += s2 * (float)acc[mi][ng][2];
            v1.y += s2 * (float)acc[mi][ng][3];
            *(float2*)(base + (size_t)o0 * HW) = v0;
            *(float2*)(base + (size_t)o1 * HW) = v1;
        }
    }
}

// ======================================================================
// launch
// ======================================================================
extern "C" void kernel_launch(void* const* d_in, const int* in_sizes, int n_in,
                              void* d_out, int out_size)
{
    const float* x  = nullptr;   // 8388608
    const float* wp = nullptr;   // 20736
    const float* bp = nullptr;   // 18
    const float* wc = nullptr;   // 294912
    for (int i = 0; i < n_in; i++) {
        switch (in_sizes[i]) {
            case 8388608: x  = (const float*)d_in[i]; break;
            case 20736:   wp = (const float*)d_in[i]; break;
            case 18:      bp = (const float*)d_in[i]; break;
            case 294912:  wc = (const float*)d_in[i]; break;
            default: break;
        }
    }
    if (!x)  x  = (const float*)d_in[0];
    if (!wp) wp = (const float*)d_in[1];
    if (!bp) bp = (const float*)d_in[2];
    if (!wc) wc = (const float*)d_in[3];

    float* out = (float*)d_out;

    cudaFuncSetAttribute(ldconv_pass1_k,
                         cudaFuncAttributeMaxDynamicSharedMemorySize, P1_TOTAL);
    cudaFuncSetAttribute(ldconv_pass2_k,
                         cudaFuncAttributeMaxDynamicSharedMemorySize, P2_TOTAL);

    wmax_k<<<64, 256>>>(wc);
    wtrans_k<<<(NT * OUTC * 16 + 255) / 256, 256>>>(wc);
    offset_conv_k<<<dim3(Hh / 2, Bb), 128>>>(x, wp, bp);
    ldconv_pass1_k<<<dim3(Hh, Bb), NTHR, P1_TOTAL>>>(x, out);
    ldconv_pass2_k<<<dim3(Hh, Bb), NTHR, P2_TOTAL>>>(out);
}

// round 10
// speedup vs baseline: 3.3216x; 3.3216x over previous
#include <cuda_runtime.h>
#include <cuda_fp16.h>
#include <cstdint>

#define Hh   128
#define Ww   128
#define HW   16384
#define Cc   128
#define NP   9
#define OUTC 256
#define Bb   4
#define BK   64
#define NT   18
#define NPXC 64
#define NTHR 256

typedef unsigned long long ull;
typedef unsigned int u32;

__device__ float g_offset[Bb * 2 * NP * HW];
__device__ __align__(128) __half g_wa[NT * OUTC * BK];

__device__ __forceinline__ u32 smem_u32(const void* p) {
    u32 a;
    asm("{ .reg .u64 t; cvta.to.shared.u64 t, %1; cvt.u32.u64 %0, t; }" : "=r"(a) : "l"(p));
    return a;
}
__device__ __forceinline__ void ldsm_x4(u32& r0, u32& r1, u32& r2, u32& r3, u32 addr) {
    asm volatile("ldmatrix.sync.aligned.m8n8.x4.shared.b16 {%0,%1,%2,%3}, [%4];"
                 : "=r"(r0), "=r"(r1), "=r"(r2), "=r"(r3) : "r"(addr));
}
__device__ __forceinline__ void mma_f16(float* d, const u32* a, const u32* b) {
    asm("mma.sync.aligned.m16n8k16.row.col.f32.f16.f16.f32 "
        "{%0,%1,%2,%3},{%4,%5,%6,%7},{%8,%9},{%0,%1,%2,%3};"
        : "+f"(d[0]), "+f"(d[1]), "+f"(d[2]), "+f"(d[3])
        : "r"(a[0]), "r"(a[1]), "r"(a[2]), "r"(a[3]), "r"(b[0]), "r"(b[1]));
}
__device__ __forceinline__ u32 swz(u32 off) { return off ^ ((off >> 3) & 0x70); }

__device__ __forceinline__ void cp_async16(u32 dst, const void* src) {
    asm volatile("cp.async.cg.shared.global [%0], [%1], 16;" :: "r"(dst), "l"(src));
}
#define CP_COMMIT() asm volatile("cp.async.commit_group;" ::: "memory")
#define CP_WAIT0()  asm volatile("cp.async.wait_group 0;" ::: "memory")

__device__ __forceinline__ void ffma2(ull& d, ull a, ull b) {
    asm("fma.rn.f32x2 %0, %1, %2, %0;" : "+l"(d) : "l"(a), "l"(b));
}
__device__ __forceinline__ ull pack2(float lo, float hi) {
    ull r; asm("mov.b64 %0, {%1, %2};" : "=l"(r) : "f"(lo), "f"(hi)); return r;
}
__device__ __forceinline__ float2 unpack2(ull v) {
    float2 f; asm("mov.b64 {%0, %1}, %2;" : "=f"(f.x), "=f"(f.y) : "l"(v)); return f;
}

// ======================================================================
__global__ void wtrans_k(const float* __restrict__ wc) {
    int i = blockIdx.x * 256 + threadIdx.x;
    if (i < NT * OUTC * BK) {
        int j = i & 63;
        int o = (i >> 6) & 255;
        int tt = i >> 14;
        int k = tt * 64 + j;
        int n = k >> 7;
        int c = k & 127;
        g_wa[i] = __float2half_rn(wc[(o * Cc + c) * NP + n]);
    }
}

// ======================================================================
__global__ void __launch_bounds__(128) offset_conv_k(
    const float* __restrict__ x,
    const float* __restrict__ wp,
    const float* __restrict__ bp)
{
    const int y0 = blockIdx.x * 2;
    const int b  = blockIdx.y;
    const int tx = threadIdx.x;

    __shared__ float xr[4][132];
    __shared__ float ws2[9][18];

    ull acc0[9], acc1[9];
#pragma unroll
    for (int p = 0; p < 9; p++) { acc0[p] = 0ULL; acc1[p] = 0ULL; }

    const float* xb = x + (size_t)b * Cc * HW;

    for (int c = 0; c < Cc; c++) {
        __syncthreads();
        for (int i = tx; i < 162; i += 128) {
            int k  = i / 18;
            int ch = i % 18;
            ws2[k][ch] = wp[ch * (Cc * 9) + c * 9 + k];
        }
        for (int i = tx; i < 4 * 132; i += 128) {
            int r  = i / 132;
            int cc = i % 132;
            int yy = y0 + r - 1;
            int xx = cc - 1;
            float v = 0.f;
            if (yy >= 0 && yy < Hh && xx >= 0 && xx < Ww)
                v = xb[c * HW + yy * Ww + xx];
            xr[r][cc] = v;
        }
        __syncthreads();

#pragma unroll
        for (int k = 0; k < 9; k++) {
            const int ky = k / 3, kx = k % 3;
            float xv0 = xr[ky][tx + kx];
            float xv1 = xr[ky + 1][tx + kx];
            ull x0d = pack2(xv0, xv0);
            ull x1d = pack2(xv1, xv1);
            const ull* wrow = (const ull*)&ws2[k][0];
#pragma unroll
            for (int p = 0; p < 9; p++) {
                ull wpair = wrow[p];
                ffma2(acc0[p], wpair, x0d);
                ffma2(acc1[p], wpair, x1d);
            }
        }
    }

#pragma unroll
    for (int p = 0; p < 9; p++) {
        float2 a0 = unpack2(acc0[p]);
        float2 a1 = unpack2(acc1[p]);
        int ch0 = 2 * p, ch1 = 2 * p + 1;
        float b0 = bp[ch0], b1 = bp[ch1];
        g_offset[((b * 18 + ch0) * Hh + y0) * Ww + tx]     = a0.x + b0;
        g_offset[((b * 18 + ch1) * Hh + y0) * Ww + tx]     = a0.y + b1;
        g_offset[((b * 18 + ch0) * Hh + y0 + 1) * Ww + tx] = a1.x + b0;
        g_offset[((b * 18 + ch1) * Hh + y0 + 1) * Ww + tx] = a1.y + b1;
    }
}

// ======================================================================
#define S_META  0
#define S_BUF0  13824
#define S_BUFSZ 40960
#define S_BH    32768
#define S_TOTAL (S_BUF0 + 2 * S_BUFSZ)     // 95744

__global__ void __launch_bounds__(NTHR, 2)
ldconv_main_k(const float* __restrict__ x, float* __restrict__ out)
{
    extern __shared__ char smem[];
    const u32 sb = smem_u32(smem);
    const int t = threadIdx.x;
    const int wid = t >> 5;
    const int lane = t & 31;
    const int px0 = blockIdx.x * NPXC;
    const int y = blockIdx.y;
    const int b = blockIdx.z;

    float4*  metaw = (float4*)(smem);
    ushort4* metai = (ushort4*)(smem + 9216);
    for (int task = t; task < NP * NPXC; task += NTHR) {
        int n  = task >> 6;
        int px = task & 63;
        int xx = px0 + px;
        float offr = g_offset[((b * 18 + n) * Hh + y) * Ww + xx];
        float offc = g_offset[((b * 18 + NP + n) * Hh + y) * Ww + xx];
        float pr = (float)y  + (float)(n / 3) + offr;
        float pc = (float)xx + (float)(n % 3) + offc;

        float ltr = floorf(pr), ltc = floorf(pc);
        float rbr = ltr + 1.f,  rbc = ltc + 1.f;
        ltr = fminf(fmaxf(ltr, 0.f), 127.f);
        rbr = fminf(fmaxf(rbr, 0.f), 127.f);
        ltc = fminf(fmaxf(ltc, 0.f), 127.f);
        rbc = fminf(fmaxf(rbc, 0.f), 127.f);
        pr  = fminf(fmaxf(pr, 0.f), 127.f);
        pc  = fminf(fmaxf(pc, 0.f), 127.f);

        float dr_lt = 1.f + (ltr - pr);
        float dr_rb = 1.f - (rbr - pr);
        float dc_lt = 1.f + (ltc - pc);
        float dc_rb = 1.f - (rbc - pc);

        float4 g;
        g.x = dr_lt * dc_lt;
        g.y = dr_rb * dc_rb;
        g.z = dr_lt * dc_rb;
        g.w = dr_rb * dc_lt;
        metaw[task] = g;

        int iltr = (int)ltr, iltc = (int)ltc;
        int irbr = (int)rbr, irbc = (int)rbc;
        ushort4 iv;
        iv.x = (unsigned short)(iltr * Ww + iltc);
        iv.y = (unsigned short)(irbr * Ww + irbc);
        iv.z = (unsigned short)(iltr * Ww + irbc);
        iv.w = (unsigned short)(irbr * Ww + iltc);
        metai[task] = iv;
    }
    __syncthreads();

    const float* xb = x + (size_t)b * Cc * HW;
    const int px = t & 63;
    const int kq = t >> 6;

    float acc[4][4][4];
#pragma unroll
    for (int i = 0; i < 4; i++)
#pragma unroll
        for (int j = 0; j < 4; j++)
#pragma unroll
            for (int q = 0; q < 4; q++) acc[i][j][q] = 0.f;

    const int bo = (wid & 3) * 64;
    const int bn = (wid >> 2) * 32;

    auto fillA_async = [&](int tile) {
        const u32 dst = sb + S_BUF0 + (u32)(tile & 1) * S_BUFSZ;
        const uint4* src = (const uint4*)(g_wa + (size_t)tile * OUTC * BK);
#pragma unroll
        for (int i = 0; i < 8; i++) {
            int e = t + i * NTHR;
            cp_async16(dst + swz((u32)(e * 16)), src + e);
        }
        CP_COMMIT();
    };

    float4 gw; ushort4 gi; const float* xc = xb;
    auto setmeta = [&](int tile) {
        const int kg0 = tile * BK + kq * 16;
        const int n   = kg0 >> 7;
        const int c0  = kg0 & 127;
        gw = metaw[n * 64 + px];
        gi = metai[n * 64 + px];
        xc = xb + (size_t)c0 * HW;
    };
    auto ldgu = [&](int u, float* f) {
#pragma unroll
        for (int jj = 0; jj < 4; jj++) {
            const float* p = xc + (size_t)(u * 4 + jj) * HW;
            f[jj * 4 + 0] = __ldg(p + gi.x);
            f[jj * 4 + 1] = __ldg(p + gi.y);
            f[jj * 4 + 2] = __ldg(p + gi.z);
            f[jj * 4 + 3] = __ldg(p + gi.w);
        }
    };
    auto cmb_sts = [&](int tile, int u, const float* f) {
        float v0 = gw.x * f[0]  + gw.y * f[1]  + gw.z * f[2]  + gw.w * f[3];
        float v1 = gw.x * f[4]  + gw.y * f[5]  + gw.z * f[6]  + gw.w * f[7];
        float v2 = gw.x * f[8]  + gw.y * f[9]  + gw.z * f[10] + gw.w * f[11];
        float v3 = gw.x * f[12] + gw.y * f[13] + gw.z * f[14] + gw.w * f[15];
        u32 p0, p1;
        asm("cvt.rn.f16x2.f32 %0, %1, %2;" : "=r"(p0) : "f"(v1), "f"(v0));
        asm("cvt.rn.f16x2.f32 %0, %1, %2;" : "=r"(p1) : "f"(v3), "f"(v2));
        char* base = smem + S_BUF0 + (size_t)(tile & 1) * S_BUFSZ + S_BH;
        *(uint2*)(base + swz((u32)(px * 128 + kq * 32 + u * 8))) = make_uint2(p0, p1);
    };

    auto compute = [&](int tile, bool gnext) {
        const u32 buf  = sb + S_BUF0 + (u32)(tile & 1) * S_BUFSZ;
        const u32 bufB = buf + S_BH;
        u32 a[4][4], bf[4][2];
#pragma unroll
        for (int ks = 0; ks < 4; ks++) {
            float f[16];
            if (gnext) ldgu(ks, f);
#pragma unroll
            for (int j = 0; j < 2; j++) {
                int nrow = bn + j * 16 + (lane & 7) + ((lane >> 4) << 3);
                int kb   = ks * 32 + ((lane >> 3) & 1) * 16;
                u32 sw = swz((u32)(nrow * 128 + kb));
                ldsm_x4(bf[2*j][0], bf[2*j][1], bf[2*j+1][0], bf[2*j+1][1], bufB + sw);
            }
#pragma unroll
            for (int mi = 0; mi < 4; mi++) {
                int ar = bo + mi * 16 + (lane & 15);
                int kb = ks * 32 + (lane >> 4) * 16;
                u32 sw = swz((u32)(ar * 128 + kb));
                ldsm_x4(a[mi][0], a[mi][1], a[mi][2], a[mi][3], buf + sw);
            }
#pragma unroll
            for (int mi = 0; mi < 4; mi++)
#pragma unroll
                for (int nt = 0; nt < 4; nt++)
                    mma_f16(acc[mi][nt], a[mi], bf[nt]);
            if (gnext) cmb_sts(tile + 1, ks, f);
        }
    };

    fillA_async(0);
    setmeta(0);
    {
        float f[16];
#pragma unroll
        for (int u = 0; u < 4; u++) { ldgu(u, f); cmb_sts(0, u, f); }
    }
    CP_WAIT0();
    __syncthreads();

    for (int tile = 0; tile < NT; tile++) {
        const bool nx = (tile + 1 < NT);
        if (nx) { fillA_async(tile + 1); setmeta(tile + 1); }
        compute(tile, nx);
        CP_WAIT0();
        __syncthreads();
    }

    const int g  = lane >> 2;
    const int tg = lane & 3;
#pragma unroll
    for (int mi = 0; mi < 4; mi++) {
#pragma unroll
        for (int nt = 0; nt < 4; nt++) {
            int pxo = px0 + bn + nt * 8 + 2 * tg;
            int o0  = bo + mi * 16 + g;
            int o1  = o0 + 8;
            float* base = out + (size_t)b * OUTC * HW + y * Ww + pxo;
            *(float2*)(base + (size_t)o0 * HW) = make_float2(acc[mi][nt][0], acc[mi][nt][1]);
            *(float2*)(base + (size_t)o1 * HW) = make_float2(acc[mi][nt][2], acc[mi][nt][3]);
        }
    }
}

// ======================================================================
extern "C" void kernel_launch(void* const* d_in, const int* in_sizes, int n_in,
                              void* d_out, int out_size)
{
    const float* x  = nullptr;
    const float* wp = nullptr;
    const float* bp = nullptr;
    const float* wc = nullptr;
    for (int i = 0; i < n_in; i++) {
        switch (in_sizes[i]) {
            case 8388608: x  = (const float*)d_in[i]; break;
            case 20736:   wp = (const float*)d_in[i]; break;
            case 18:      bp = (const float*)d_in[i]; break;
            case 294912:  wc = (const float*)d_in[i]; break;
            default: break;
        }
    }
    if (!x)  x  = (const float*)d_in[0];
    if (!wp) wp = (const float*)d_in[1];
    if (!bp) bp = (const float*)d_in[2];
    if (!wc) wc = (const float*)d_in[3];

    float* out = (float*)d_out;

    cudaFuncSetAttribute(ldconv_main_k,
                         cudaFuncAttributeMaxDynamicSharedMemorySize, S_TOTAL);

    wtrans_k<<<(NT * OUTC * BK + 255) / 256, 256>>>(wc);
    offset_conv_k<<<dim3(Hh / 2, Bb), 128>>>(x, wp, bp);
    ldconv_main_k<<<dim3(Ww / NPXC, Hh, Bb), NTHR, S_TOTAL>>>(x, out);
}